// round 14
// baseline (speedup 1.0000x reference)
#include <cuda_runtime.h>
#include <cstdint>

#define NPTS  8192
#define BATCH 2
#define KNN   30
#define NTHREADS 1024
#define NBLOCKS  148
#define MAXF 3.4028234663852886e38f
#define NCELL 4096          // 16x16x16 grid, Morton order
#define NTILE (NPTS / 32)   // 256 tiles of 32 sorted points

#define SM_PTS   0
#define SM_IDX   (NPTS * 16)
#define SM_BLO   (SM_IDX + NPTS * 4)
#define SM_BHI   (SM_BLO + NTILE * 16)
#define SM_MSK   (SM_BHI + NTILE * 16)
#define SMEM_BYTES (SM_MSK + (NPTS / 32) * 4)

typedef unsigned long long u64;
#define SENT64 0xffffffffffffffffULL

// Scratch (no cudaMalloc allowed).
__device__ float4   g_pts [BATCH * NPTS];
__device__ unsigned g_msk [BATCH * NPTS / 32];
__device__ unsigned g_ctr [BATCH];
__device__ float4   g_spts[BATCH * NPTS];
__device__ int      g_sidx[BATCH * NPTS];
__device__ unsigned g_pos [BATCH * NPTS];

__global__ void prep_kernel(const float* __restrict__ X, const int* __restrict__ C) {
    int p = blockIdx.x * blockDim.x + threadIdx.x;
    if (p < BATCH) g_ctr[p] = 0;
    float x = X[p * 3 + 0], y = X[p * 3 + 1], z = X[p * 3 + 2];
    // XLA GPU row-reduce butterfly: x2 = rn(rn(x^2 + z^2) + y^2)   (bit-exact match)
    float x2 = __fadd_rn(__fadd_rn(__fmul_rn(x, x), __fmul_rn(z, z)), __fmul_rn(y, y));
    unsigned bit = (C[p] > 0) ? 1u : 0u;
    if (!bit) x2 = __int_as_float(0x7f800000);   // poison: d2=+inf downstream
    g_pts[p] = make_float4(x, y, z, x2);
    unsigned word = __ballot_sync(0xffffffffu, bit);
    if ((threadIdx.x & 31) == 0) g_msk[p >> 5] = word;
}

__device__ __forceinline__ unsigned part3(unsigned v) {
    return (v & 1u) | ((v & 2u) << 2) | ((v & 4u) << 4) | ((v & 8u) << 6);
}
__device__ __forceinline__ unsigned cellof(float c) {
    int v = (int)floorf((c + 50.0f) * 0.16f);
    return (unsigned)max(0, min(15, v));
}

// Counting sort into Morton-ordered cells (order-invariant result downstream).
__global__ void __launch_bounds__(1024) sort_kernel() {
    __shared__ unsigned hist[NCELL];
    __shared__ unsigned chunk[1024];
    const int bid = blockIdx.x, t = threadIdx.x;
    const float4* src = g_pts + bid * NPTS;

    for (int c = t; c < NCELL; c += 1024) hist[c] = 0;
    __syncthreads();

    unsigned cells[8];
    #pragma unroll
    for (int k = 0; k < 8; k++) {
        int p = t + k * 1024;
        float4 v = src[p];
        unsigned m = part3(cellof(v.x)) | (part3(cellof(v.y)) << 1) | (part3(cellof(v.z)) << 2);
        cells[k] = m;
        atomicAdd(&hist[m], 1u);
    }
    __syncthreads();

    unsigned a0 = hist[4*t], a1 = hist[4*t+1], a2 = hist[4*t+2], a3 = hist[4*t+3];
    unsigned s = a0 + a1 + a2 + a3;
    chunk[t] = s;
    __syncthreads();
    for (int off = 1; off < 1024; off <<= 1) {
        unsigned u = (t >= off) ? chunk[t - off] : 0u;
        __syncthreads();
        chunk[t] += u;
        __syncthreads();
    }
    unsigned excl = chunk[t] - s;
    hist[4*t]     = excl;
    hist[4*t + 1] = excl + a0;
    hist[4*t + 2] = excl + a0 + a1;
    hist[4*t + 3] = excl + a0 + a1 + a2;
    __syncthreads();

    #pragma unroll
    for (int k = 0; k < 8; k++) {
        int p = t + k * 1024;
        float4 v = src[p];
        unsigned pos = atomicAdd(&hist[cells[k]], 1u);
        g_spts[bid * NPTS + pos] = v;
        g_sidx[bid * NPTS + pos] = p;
        g_pos [bid * NPTS + p]   = pos;
    }
}

extern __shared__ unsigned char smem_raw[];

__global__ void __launch_bounds__(NTHREADS) knn_kernel(float* __restrict__ out) {
    float4*   spts = (float4*)(smem_raw + SM_PTS);
    int*      sidx = (int*)   (smem_raw + SM_IDX);
    float4*   blo  = (float4*)(smem_raw + SM_BLO);
    float4*   bhi  = (float4*)(smem_raw + SM_BHI);
    unsigned* smsk = (unsigned*)(smem_raw + SM_MSK);

    const int warp = threadIdx.x >> 5;
    const int lane = threadIdx.x & 31;
    const int b = blockIdx.x & 1;

    for (int t = threadIdx.x; t < NPTS; t += NTHREADS) {
        spts[t] = g_spts[b * NPTS + t];
        sidx[t] = g_sidx[b * NPTS + t];
    }
    for (int t = threadIdx.x; t < NPTS / 32; t += NTHREADS) smsk[t] = g_msk[b * (NPTS/32) + t];
    __syncthreads();

    const float FINF = __int_as_float(0x7f800000);
    for (int tt = warp * (NTILE / 32); tt < (warp + 1) * (NTILE / 32); tt++) {
        float4 p = spts[tt * 32 + lane];
        bool valid = p.w < 1e30f;
        float mnx = valid ? p.x :  FINF, mxx = valid ? p.x : -FINF;
        float mny = valid ? p.y :  FINF, mxy = valid ? p.y : -FINF;
        float mnz = valid ? p.z :  FINF, mxz = valid ? p.z : -FINF;
        #pragma unroll
        for (int off = 16; off; off >>= 1) {
            mnx = fminf(mnx, __shfl_xor_sync(0xffffffffu, mnx, off));
            mxx = fmaxf(mxx, __shfl_xor_sync(0xffffffffu, mxx, off));
            mny = fminf(mny, __shfl_xor_sync(0xffffffffu, mny, off));
            mxy = fmaxf(mxy, __shfl_xor_sync(0xffffffffu, mxy, off));
            mnz = fminf(mnz, __shfl_xor_sync(0xffffffffu, mnz, off));
            mxz = fmaxf(mxz, __shfl_xor_sync(0xffffffffu, mxz, off));
        }
        if (lane == 0) {
            blo[tt] = make_float4(mnx, mny, mnz, 0.f);
            bhi[tt] = make_float4(mxx, mxy, mxz, 0.f);
        }
    }
    __syncthreads();

    for (;;) {
        unsigned ri;
        if (lane == 0) ri = atomicAdd(&g_ctr[b], 1u);
        ri = __shfl_sync(0xffffffffu, ri, 0);
        if (ri >= NPTS) break;
        const int i = (int)ri;
        const int r = b * NPTS + i;
        float* outIdx = out + (size_t)r * KNN;
        float* outMsk = out + (size_t)(BATCH * NPTS) * KNN + (size_t)r * KNN;

        const unsigned mi = (smsk[i >> 5] >> (i & 31)) & 1u;
        if (!mi) {
            if (lane < KNN) { outIdx[lane] = (float)lane; outMsk[lane] = 0.0f; }
            continue;
        }

        const float4 pi = g_pts[r];
        const unsigned start = g_pos[r] >> 5;

        // ── Home-tile init: bitonic ascending sort of packed keys = initial list.
        u64 lk;
        {
            const int jj = (int)start * 32 + lane;
            const float4 pj = spts[jj];
            const int j = sidx[jj];
            // exact reference arithmetic (validated bit-exact R6-R13)
            const float sd  = __fadd_rn(pi.w, pj.w);
            const float dot = fmaf(pi.z, pj.z, fmaf(pi.y, pj.y, __fmul_rn(pi.x, pj.x)));
            const float d2  = __fsub_rn(sd, __fmul_rn(2.0f, dot));
            const float Dc  = __fsqrt_rn(fmaxf(d2, 0.0f));   // +inf for invalid pj
            u64 key = ((u64)__float_as_uint(Dc) << 32) | (unsigned)j;
            #pragma unroll
            for (int k = 2; k <= 32; k <<= 1) {
                #pragma unroll
                for (int jd = k >> 1; jd > 0; jd >>= 1) {
                    const u64 o = __shfl_xor_sync(0xffffffffu, key, jd);
                    const bool up      = ((lane & k) == 0);
                    const bool takeMin = (((lane & jd) == 0) == up);
                    if (takeMin ? (o < key) : (o > key)) key = o;
                }
            }
            lk = key;
        }
        u64   k29  = __shfl_sync(0xffffffffu, lk, 29);
        float v29  = __uint_as_float((unsigned)(k29 >> 32));
        float thr2 = __fmul_rn(__fmul_rn(v29, v29), 1.00002f);

        for (int s = 0; s < NTILE / 32; s++) {
            const unsigned tt = (start + (unsigned)(s * 32 + lane)) & (NTILE - 1);
            const float4 lo = blo[tt];
            const float4 hi = bhi[tt];
            const float dx = fmaxf(fmaxf(lo.x - pi.x, pi.x - hi.x), 0.0f);
            const float dy = fmaxf(fmaxf(lo.y - pi.y, pi.y - hi.y), 0.0f);
            const float dz = fmaxf(fmaxf(lo.z - pi.z, pi.z - hi.z), 0.0f);
            const float bd2 = fmaf(dx, dx, fmaf(dy, dy, dz * dz));

            unsigned tb = __ballot_sync(0xffffffffu, bd2 * 0.9999f <= thr2);
            if (s == 0) tb &= ~1u;                   // home tile already consumed
            while (tb) {
                const int src = __ffs(tb) - 1; tb &= tb - 1;
                const float bd2t = __shfl_sync(0xffffffffu, bd2, src);
                if (bd2t * 0.9999f > thr2) continue;
                const unsigned tile = (start + (unsigned)(s * 32 + src)) & (NTILE - 1);
                const int jj = tile * 32 + lane;
                const float4 pj = spts[jj];
                const int j = sidx[jj];
                const float sd  = __fadd_rn(pi.w, pj.w);
                const float dot = fmaf(pi.z, pj.z, fmaf(pi.y, pj.y, __fmul_rn(pi.x, pj.x)));
                const float d2  = __fsub_rn(sd, __fmul_rn(2.0f, dot));

                const bool ok = (d2 < thr2);         // false for invalid (d2=+inf)
                unsigned pass = __ballot_sync(0xffffffffu, ok);
                if (!pass) continue;

                u64 ck = SENT64;
                if (ok) {
                    const float Dc = __fsqrt_rn(fmaxf(d2, 0.0f));
                    ck = ((u64)__float_as_uint(Dc) << 32) | (unsigned)j;
                }

                if (__popc(pass) >= 3) {
                    // ── Batch path: bitonic k-select merge (flat cost, any #inserts).
                    // 1) sort candidates DESCENDING across lanes
                    #pragma unroll
                    for (int k = 2; k <= 32; k <<= 1) {
                        #pragma unroll
                        for (int jd = k >> 1; jd > 0; jd >>= 1) {
                            const u64 o = __shfl_xor_sync(0xffffffffu, ck, jd);
                            const bool up      = ((lane & k) == 0);
                            const bool takeMax = (((lane & jd) == 0) == up);
                            if (takeMax ? (o > ck) : (o < ck)) ck = o;
                        }
                    }
                    // 2) elementwise min of ascending list and descending cands -> bitonic
                    if (ck < lk) lk = ck;
                    // 3) clean: 5-stage ascending bitonic merge
                    #pragma unroll
                    for (int jd = 16; jd > 0; jd >>= 1) {
                        const u64 o = __shfl_xor_sync(0xffffffffu, lk, jd);
                        const bool takeMin = ((lane & jd) == 0);
                        if (takeMin ? (o < lk) : (o > lk)) lk = o;
                    }
                    k29  = __shfl_sync(0xffffffffu, lk, 29);
                    v29  = __uint_as_float((unsigned)(k29 >> 32));
                    thr2 = __fmul_rn(__fmul_rn(v29, v29), 1.00002f);
                } else {
                    // ── Serial path (1-2 candidates)
                    unsigned bal = __ballot_sync(0xffffffffu, ok && ck < k29);
                    while (bal) {
                        const int cs = __ffs(bal) - 1; bal &= bal - 1;
                        const u64 c = __shfl_sync(0xffffffffu, ck, cs);
                        if (c < k29) {
                            const bool less = lk < c;
                            const int  p    = __popc(__ballot_sync(0xffffffffu, less));
                            const u64  up   = __shfl_up_sync(0xffffffffu, lk, 1);
                            if (lane == p)      lk = c;
                            else if (lane > p)  lk = up;
                            k29  = __shfl_sync(0xffffffffu, lk, 29);
                            v29  = __uint_as_float((unsigned)(k29 >> 32));
                            thr2 = __fmul_rn(__fmul_rn(v29, v29), 1.00002f);
                        }
                    }
                }
            }
        }

        if (lane < KNN) {
            outIdx[lane] = (float)(int)(unsigned)(lk & 0xffffffffu);
            outMsk[lane] = 1.0f;
        }
    }
}

extern "C" void kernel_launch(void* const* d_in, const int* in_sizes, int n_in,
                              void* d_out, int out_size) {
    int xi = 0, ci = 1;
    if (in_sizes[0] == BATCH * NPTS) { xi = 1; ci = 0; }
    const float* X = (const float*)d_in[xi];
    const int*   C = (const int*)d_in[ci];
    float* out = (float*)d_out;

    prep_kernel<<<(BATCH * NPTS) / 256, 256>>>(X, C);
    sort_kernel<<<BATCH, 1024>>>();

    cudaFuncSetAttribute(knn_kernel, cudaFuncAttributeMaxDynamicSharedMemorySize, SMEM_BYTES);
    knn_kernel<<<NBLOCKS, NTHREADS, SMEM_BYTES>>>(out);
}